// round 11
// baseline (speedup 1.0000x reference)
#include <cuda_runtime.h>
#include <cstdint>
#include <cstddef>

// E=16, D=1024, H=4096, N=16384 (1024 tokens/expert, contiguous).
// GEMM1: per-expert [1024 x 4096 x 1024], relu(X*W1^T + b1) -> hidden fp32
// GEMM2: per-expert [1024 x 1024 x 4096], H*W2^T + b2       -> fp32 out
// R11: int8 IMMA 3-limb fixed-point (15-bit/operand, per-row scales).
//   a ~= sa*(ah*128 + al), |al|<=64. acc1 = ah*bh, acc2 = al*bh + ah*bl (int32,
//   exact). result = sa*sb*(16384*acc1 + 128*acc2). Dropped al*bl ~ 5e-5 rel.
//   mma.m16n8k32.s8 does 2x K per instruction vs bf16 k16 at the same issue
//   rate -> tensor instruction count halves vs the bf16 3-pass (R4..R10 showed
//   ~74% tensor is an instruction-rate ceiling, so time ~ instruction count).
// SMEM geometry identical to R4: 128-byte rows (=128 int8), SW128, 3x64KB ring;
// the b16-pair view of int8 k32 fragments matches the bf16 k16 ldsm layout
// exactly, so all validated ldsm/mma addressing carries over verbatim.

static __device__ int8_t g_xa_h[16777216],  g_xa_l[16777216];
static __device__ int8_t g_w1_h[67108864],  g_w1_l[67108864];
static __device__ int8_t g_w2_h[67108864],  g_w2_l[67108864];
static __device__ int8_t g_ha_h[67108864],  g_ha_l[67108864];
static __device__ float  g_xa_s[16384], g_w1_s[65536], g_w2_s[16384], g_ha_s[16384];
static __device__ float  g_hidden[(size_t)16384 * 4096];  // fp32 hidden

__device__ __forceinline__ uint32_t smem_u32(const void* p) {
    uint32_t a;
    asm("{ .reg .u64 t; cvta.to.shared.u64 t, %1; cvt.u32.u64 %0, t; }"
        : "=r"(a) : "l"(p));
    return a;
}
#define SW128(x) ((x) ^ (((x) >> 3) & 0x70))

__device__ __forceinline__ void ldsm4(uint32_t* r, uint32_t addr) {
    asm volatile("ldmatrix.sync.aligned.m8n8.x4.shared.b16 {%0,%1,%2,%3}, [%4];"
                 : "=r"(r[0]), "=r"(r[1]), "=r"(r[2]), "=r"(r[3]) : "r"(addr));
}
__device__ __forceinline__ void imma16832(int* c, const uint32_t* a,
                                          uint32_t b0, uint32_t b1) {
    asm volatile(
        "mma.sync.aligned.m16n8k32.row.col.s32.s8.s8.s32 "
        "{%0,%1,%2,%3}, {%4,%5,%6,%7}, {%8,%9}, {%0,%1,%2,%3};"
        : "+r"(c[0]), "+r"(c[1]), "+r"(c[2]), "+r"(c[3])
        : "r"(a[0]), "r"(a[1]), "r"(a[2]), "r"(a[3]), "r"(b0), "r"(b1));
}
__device__ __forceinline__ void cp16(uint32_t dst, const void* src) {
    asm volatile("cp.async.cg.shared.global [%0], [%1], 16;"
                 :: "r"(dst), "l"(src) : "memory");
}
#define CP_COMMIT() asm volatile("cp.async.commit_group;" ::: "memory")
#define CP_WAIT1()  asm volatile("cp.async.wait_group 1;" ::: "memory")

// -------- per-row 15-bit 2-limb int8 quantization --------
// row scale s = rowmax/16256; q = a/s in [-16256,16256]; h = rn(q/128) in
// [-127,127]; l = rn(q - 128h) in [-64,64].
template <int K>
__global__ __launch_bounds__(256)
void quant_rows(const float* __restrict__ in, int8_t* __restrict__ hi,
                int8_t* __restrict__ lo, float* __restrict__ sc) {
    constexpr int PER = K / 256;  // elems per thread (4 or 16), mult of 4
    const size_t base = (size_t)blockIdx.x * K;
    const int tid = threadIdx.x;
    const float4* rowv = (const float4*)(in + base);

    float v[PER];
    float mx = 0.f;
#pragma unroll
    for (int t = 0; t < PER / 4; t++) {
        float4 f = rowv[tid + t * 256];
        v[4 * t + 0] = f.x; v[4 * t + 1] = f.y;
        v[4 * t + 2] = f.z; v[4 * t + 3] = f.w;
        mx = fmaxf(mx, fmaxf(fmaxf(fabsf(f.x), fabsf(f.y)),
                             fmaxf(fabsf(f.z), fabsf(f.w))));
    }
#pragma unroll
    for (int o = 16; o; o >>= 1) mx = fmaxf(mx, __shfl_xor_sync(0xFFFFFFFFu, mx, o));
    __shared__ float wmax[8];
    if ((tid & 31) == 0) wmax[tid >> 5] = mx;
    __syncthreads();
    float m = wmax[0];
#pragma unroll
    for (int w = 1; w < 8; w++) m = fmaxf(m, wmax[w]);

    const float inv = (m > 0.f) ? (16256.f / m) : 0.f;
    if (tid == 0) sc[blockIdx.x] = m * (1.f / 16256.f);

    uint32_t* hp = (uint32_t*)(hi + base);
    uint32_t* lp = (uint32_t*)(lo + base);
#pragma unroll
    for (int t = 0; t < PER / 4; t++) {
        uint32_t hw = 0, lw = 0;
#pragma unroll
        for (int j = 0; j < 4; j++) {
            float q = v[4 * t + j] * inv;
            int h = __float2int_rn(q * 0.0078125f);       // q/128
            int l = __float2int_rn(q - 128.f * (float)h);
            hw |= ((uint32_t)h & 0xFFu) << (8 * j);
            lw |= ((uint32_t)l & 0xFFu) << (8 * j);
        }
        hp[tid + t * 256] = hw;
        lp[tid + t * 256] = lw;
    }
}

// SMEM stage (int8, 128-elem rows = 128B, SW128):
//   Ahi @0 (16KB)  Alo @16384  Bhi @32768  Blo @49152  -> 64KB/stage, 3 stages
static constexpr int STAGE = 65536;
static constexpr int SMEM_TOTAL = 3 * STAGE;  // 192 KB

template <int NCOLS, int KDIM, bool RELU>
__global__ __launch_bounds__(256, 1)
void ffn_imma(const int8_t* __restrict__ Ah, const int8_t* __restrict__ Al,
              const float* __restrict__ As,   // A row scales [E*1024]
              const int8_t* __restrict__ Bh, const int8_t* __restrict__ Bl,
              const float* __restrict__ Bs,   // B row scales [E*NCOLS]
              const float* __restrict__ bias,
              float* __restrict__ C)
{
    constexpr int NK = KDIM / 128;  // 128 int8 per stage row
    extern __shared__ char smem[];
    const uint32_t smb = smem_u32(smem);

    const int tid  = threadIdx.x;
    const int lane = tid & 31, warp = tid >> 5;
    const int wm = warp >> 2, wn = warp & 3;  // 2x4, warp tile 64(M) x 32(N)
    const int e  = blockIdx.z;
    const int m0 = blockIdx.y * 128, n0 = blockIdx.x * 128;

    const int8_t* Abh = Ah + ((size_t)e * 1024 + m0) * KDIM;
    const int8_t* Abl = Al + ((size_t)e * 1024 + m0) * KDIM;
    const int8_t* Bbh = Bh + ((size_t)e * NCOLS + n0) * KDIM;
    const int8_t* Bbl = Bl + ((size_t)e * NCOLS + n0) * KDIM;

    // staging: 16B chunks; each plane = 128 rows x 128B = 1024 chunks, 4/thread
    int sws[4], goff[4];
#pragma unroll
    for (int t = 0; t < 4; t++) {
        int s = tid + (t << 8);
        int row = s >> 3, c = s & 7;
        sws[t]  = SW128(row * 128 + c * 16);
        goff[t] = row * KDIM + c * 16;  // bytes (int8 == elems)
    }

    // ldsm bases: identical to validated bf16 path (rows are 128B either way)
    const int xmask = (lane & 7) << 4;
    const int a_b0 = (wm * 64 + (lane & 15)) * 128 + ((lane >> 4) & 1) * 16;
    const int b_b0 = (wn * 32 + (lane & 7) + ((lane >> 4) & 1) * 8) * 128 +
                     ((lane >> 3) & 1) * 16;

    int acc1[4][4][4], acc2[4][4][4];
#pragma unroll
    for (int i = 0; i < 4; i++)
#pragma unroll
        for (int j = 0; j < 4; j++)
#pragma unroll
            for (int q = 0; q < 4; q++) { acc1[i][j][q] = 0; acc2[i][j][q] = 0; }

    auto stage = [&](int kt, uint32_t base) {
        const int kofs = kt * 128;
#pragma unroll
        for (int t = 0; t < 4; t++) {
            const int g = goff[t] + kofs;
            cp16(base + sws[t],          Abh + g);
            cp16(base + 16384 + sws[t],  Abl + g);
            cp16(base + 32768 + sws[t],  Bbh + g);
            cp16(base + 49152 + sws[t],  Bbl + g);
        }
    };

    stage(0, smb);         CP_COMMIT();
    stage(1, smb + STAGE); CP_COMMIT();
    CP_WAIT1();
    __syncthreads();

    for (int kt = 0; kt < NK; ++kt) {
        const uint32_t sA = smb + (kt % 3) * STAGE;

        if (kt + 2 < NK) stage(kt + 2, smb + ((kt + 2) % 3) * STAGE);
        CP_COMMIT();

#pragma unroll
        for (int kk = 0; kk < 4; kk++) {  // 4 x k32 per 128B row
            uint32_t ah[4][4], al[4][4], b[2][4];
#pragma unroll
            for (int mt = 0; mt < 4; mt++) {
                int off = (a_b0 + mt * 2048 + kk * 32) ^ xmask;
                ldsm4(ah[mt], sA + off);
                ldsm4(al[mt], sA + 16384 + off);
            }
#pragma unroll
            for (int nt2 = 0; nt2 < 2; nt2++) {
                int off = (b_b0 + nt2 * 2048 + kk * 32) ^ xmask;
                ldsm4(b[nt2], sA + 32768 + off);  // B hi
            }
#pragma unroll
            for (int mt = 0; mt < 4; mt++)
#pragma unroll
                for (int nt = 0; nt < 4; nt++) {
                    const int g = nt >> 1, s2 = (nt & 1) * 2;
                    imma16832(acc1[mt][nt], ah[mt], b[g][s2], b[g][s2 + 1]);
                    imma16832(acc2[mt][nt], al[mt], b[g][s2], b[g][s2 + 1]);
                }
#pragma unroll
            for (int nt2 = 0; nt2 < 2; nt2++) {
                int off = (b_b0 + nt2 * 2048 + kk * 32) ^ xmask;
                ldsm4(b[nt2], sA + 49152 + off);  // B lo (reuse regs)
            }
#pragma unroll
            for (int mt = 0; mt < 4; mt++)
#pragma unroll
                for (int nt = 0; nt < 4; nt++) {
                    const int g = nt >> 1, s2 = (nt & 1) * 2;
                    imma16832(acc2[mt][nt], ah[mt], b[g][s2], b[g][s2 + 1]);
                }
        }

        if (kt + 1 < NK) {
            CP_WAIT1();
            __syncthreads();
        }
    }

    // ---- epilogue: dequant + bias (+relu) ----
    const size_t rbase = (size_t)e * 1024 + m0 + wm * 64;
    const int cb = n0 + wn * 32 + (lane & 3) * 2;
    const float* bsp = Bs + (size_t)e * NCOLS + cb;
    const float* bp  = bias + (size_t)e * NCOLS + cb;
#pragma unroll
    for (int mt = 0; mt < 4; mt++) {
        int r = mt * 16 + (lane >> 2);
        float sa0 = As[rbase + r], sa1 = As[rbase + r + 8];
#pragma unroll
        for (int nt = 0; nt < 4; nt++) {
            float2 sb = *(const float2*)(bsp + nt * 8);
            float2 bv = *(const float2*)(bp + nt * 8);
            float d0 = fmaf(16384.f, (float)acc1[mt][nt][0], 128.f * (float)acc2[mt][nt][0]);
            float d1 = fmaf(16384.f, (float)acc1[mt][nt][1], 128.f * (float)acc2[mt][nt][1]);
            float d2 = fmaf(16384.f, (float)acc1[mt][nt][2], 128.f * (float)acc2[mt][nt][2]);
            float d3 = fmaf(16384.f, (float)acc1[mt][nt][3], 128.f * (float)acc2[mt][nt][3]);
            float2 v0, v1;
            v0.x = sa0 * sb.x * d0 + bv.x;
            v0.y = sa0 * sb.y * d1 + bv.y;
            v1.x = sa1 * sb.x * d2 + bv.x;
            v1.y = sa1 * sb.y * d3 + bv.y;
            if (RELU) {
                v0.x = fmaxf(v0.x, 0.f); v0.y = fmaxf(v0.y, 0.f);
                v1.x = fmaxf(v1.x, 0.f); v1.y = fmaxf(v1.y, 0.f);
            }
            const int col = cb + nt * 8;
            *(float2*)(C + (rbase + r) * NCOLS + col)     = v0;
            *(float2*)(C + (rbase + r + 8) * NCOLS + col) = v1;
        }
    }
}

extern "C" void kernel_launch(void* const* d_in, const int* in_sizes, int n_in,
                              void* d_out, int out_size) {
    (void)in_sizes; (void)n_in; (void)out_size;
    const float* xs = (const float*)d_in[0];
    const float* w1 = (const float*)d_in[2];
    const float* b1 = (const float*)d_in[3];
    const float* w2 = (const float*)d_in[4];
    const float* b2 = (const float*)d_in[5];
    float* out = (float*)d_out;

    void *xah, *xal, *xas, *w1h, *w1l, *w1s, *w2h, *w2l, *w2s, *hah, *hal, *has, *hid;
    cudaGetSymbolAddress(&xah, g_xa_h); cudaGetSymbolAddress(&xal, g_xa_l);
    cudaGetSymbolAddress(&xas, g_xa_s);
    cudaGetSymbolAddress(&w1h, g_w1_h); cudaGetSymbolAddress(&w1l, g_w1_l);
    cudaGetSymbolAddress(&w1s, g_w1_s);
    cudaGetSymbolAddress(&w2h, g_w2_h); cudaGetSymbolAddress(&w2l, g_w2_l);
    cudaGetSymbolAddress(&w2s, g_w2_s);
    cudaGetSymbolAddress(&hah, g_ha_h); cudaGetSymbolAddress(&hal, g_ha_l);
    cudaGetSymbolAddress(&has, g_ha_s);
    cudaGetSymbolAddress(&hid, g_hidden);

    cudaFuncSetAttribute(ffn_imma<4096, 1024, true>,
                         cudaFuncAttributeMaxDynamicSharedMemorySize, SMEM_TOTAL);
    cudaFuncSetAttribute(ffn_imma<1024, 4096, false>,
                         cudaFuncAttributeMaxDynamicSharedMemorySize, SMEM_TOTAL);

    // quantize inputs/weights (per K-major row)
    quant_rows<1024><<<16384, 256>>>(xs, (int8_t*)xah, (int8_t*)xal, (float*)xas);
    quant_rows<1024><<<65536, 256>>>(w1, (int8_t*)w1h, (int8_t*)w1l, (float*)w1s);
    quant_rows<4096><<<16384, 256>>>(w2, (int8_t*)w2h, (int8_t*)w2l, (float*)w2s);

    // GEMM1 -> fp32 hidden (bias+relu)
    ffn_imma<4096, 1024, true><<<dim3(32, 8, 16), 256, SMEM_TOTAL>>>(
        (const int8_t*)xah, (const int8_t*)xal, (const float*)xas,
        (const int8_t*)w1h, (const int8_t*)w1l, (const float*)w1s,
        b1, (float*)hid);

    // quantize hidden rows (K=4096)
    quant_rows<4096><<<16384, 256>>>((const float*)hid,
                                     (int8_t*)hah, (int8_t*)hal, (float*)has);

    // GEMM2 -> fp32 out (bias)
    ffn_imma<1024, 4096, false><<<dim3(8, 8, 16), 256, SMEM_TOTAL>>>(
        (const int8_t*)hah, (const int8_t*)hal, (const float*)has,
        (const int8_t*)w2h, (const int8_t*)w2l, (const float*)w2s,
        b2, out);
}

// round 12
// speedup vs baseline: 3.8768x; 3.8768x over previous
#include <cuda_runtime.h>
#include <cuda_fp16.h>
#include <cstdint>
#include <cstddef>

// E=16, D=1024, H=4096, N=16384 (1024 tokens/expert, contiguous).
// GEMM1: per-expert [1024 x 4096 x 1024], relu(X*W1^T + b1) -> hidden (fp16 h/l)
// GEMM2: per-expert [1024 x 1024 x 4096], H*W2^T + b2       -> fp32 out
// R12: fp16 2-pass. Activations split a = ah + al (fp16 pair, ~22-bit exact);
// weights single fp16. (ah+al)*bh = a*bh with both passes accumulating into
// ONE fp32 accumulator -> 2/3 the HMMA count of the bf16 3-pass at the same
// issue rate (R4..R10: time ~ tensor instruction count at the ~74% ceiling).
// Error = a*(b - fp16(b)) ~ 1.4e-4 RMS per GEMM -> ~2e-4 total (<< 1e-3).
// Geometry = validated R4: BM=128,BN=128,BK=64, 256 thr, SW128, cp.async ring
// (3 planes x 16KB = 48KB/stage, 3 stages).

static __device__ __half g_xs_h[16777216], g_xs_l[16777216];
static __device__ __half g_w1_h[67108864];
static __device__ __half g_w2_h[67108864];
static __device__ __half g_hid_h[67108864], g_hid_l[67108864];

__device__ __forceinline__ uint32_t smem_u32(const void* p) {
    uint32_t a;
    asm("{ .reg .u64 t; cvta.to.shared.u64 t, %1; cvt.u32.u64 %0, t; }"
        : "=r"(a) : "l"(p));
    return a;
}
#define SW128(x) ((x) ^ (((x) >> 3) & 0x70))

// lower half = fp16(a), upper half = fp16(b)
__device__ __forceinline__ uint32_t pack_h2(float a, float b) {
    uint32_t r;
    asm("cvt.rn.f16x2.f32 %0, %1, %2;" : "=r"(r) : "f"(b), "f"(a));
    return r;
}
__device__ __forceinline__ void ldsm4(uint32_t* r, uint32_t addr) {
    asm volatile("ldmatrix.sync.aligned.m8n8.x4.shared.b16 {%0,%1,%2,%3}, [%4];"
                 : "=r"(r[0]), "=r"(r[1]), "=r"(r[2]), "=r"(r[3]) : "r"(addr));
}
__device__ __forceinline__ void mma_f16(float* c, const uint32_t* a,
                                        uint32_t b0, uint32_t b1) {
    asm volatile(
        "mma.sync.aligned.m16n8k16.row.col.f32.f16.f16.f32 "
        "{%0,%1,%2,%3}, {%4,%5,%6,%7}, {%8,%9}, {%0,%1,%2,%3};"
        : "+f"(c[0]), "+f"(c[1]), "+f"(c[2]), "+f"(c[3])
        : "r"(a[0]), "r"(a[1]), "r"(a[2]), "r"(a[3]), "r"(b0), "r"(b1));
}
__device__ __forceinline__ void cp16(uint32_t dst, const void* src) {
    asm volatile("cp.async.cg.shared.global [%0], [%1], 16;"
                 :: "r"(dst), "l"(src) : "memory");
}
#define CP_COMMIT() asm volatile("cp.async.commit_group;" ::: "memory")
#define CP_WAIT1()  asm volatile("cp.async.wait_group 1;" ::: "memory")

// -------- fp32 -> fp16 hi/lo split (activations) --------
__global__ __launch_bounds__(256)
void split_f16_k(const float4* __restrict__ in, uint2* __restrict__ hi,
                 uint2* __restrict__ lo, int n4) {
    int i = blockIdx.x * 256 + threadIdx.x;
    if (i >= n4) return;
    float4 f = in[i];
    float v[4] = {f.x, f.y, f.z, f.w};
    float h[4], l[4];
#pragma unroll
    for (int j = 0; j < 4; j++) {
        __half hh = __float2half_rn(v[j]);
        h[j] = __half2float(hh);
        l[j] = v[j] - h[j];
    }
    hi[i] = make_uint2(pack_h2(h[0], h[1]), pack_h2(h[2], h[3]));
    lo[i] = make_uint2(pack_h2(l[0], l[1]), pack_h2(l[2], l[3]));
}

// -------- fp32 -> single fp16 (weights) --------
__global__ __launch_bounds__(256)
void conv_f16_k(const float4* __restrict__ in, uint2* __restrict__ out, int n4) {
    int i = blockIdx.x * 256 + threadIdx.x;
    if (i >= n4) return;
    float4 f = in[i];
    out[i] = make_uint2(pack_h2(f.x, f.y), pack_h2(f.z, f.w));
}

// SMEM stage (fp16, 64-elem rows = 128B, SW128):
//   Ahi @0 (16KB)  Alo @16384  Bhi @32768  -> 48KB/stage, 3 stages
static constexpr int A_LO = 16384, B_HI = 32768;
static constexpr int STAGE = 49152;
static constexpr int SMEM_TOTAL = 3 * STAGE;  // 144 KB

template <int NCOLS, int KDIM, bool RELU, bool SPLIT>
__global__ __launch_bounds__(256, 1)
void ffn_h2(const __half* __restrict__ Ah, const __half* __restrict__ Al,
            const __half* __restrict__ Bh,
            const float* __restrict__ bias,
            float* __restrict__ Cf,
            __half* __restrict__ Ch, __half* __restrict__ Cl)
{
    constexpr int NK = KDIM / 64;
    extern __shared__ char smem[];
    const uint32_t smb = smem_u32(smem);

    const int tid  = threadIdx.x;
    const int lane = tid & 31, warp = tid >> 5;
    const int wm = warp >> 2, wn = warp & 3;  // 2x4, warp tile 64(M) x 32(N)
    const int e  = blockIdx.z;
    const int m0 = blockIdx.y * 128, n0 = blockIdx.x * 128;

    const __half* Abh = Ah + ((size_t)e * 1024 + m0) * KDIM;
    const __half* Abl = Al + ((size_t)e * 1024 + m0) * KDIM;
    const __half* Bbh = Bh + ((size_t)e * NCOLS + n0) * KDIM;

    // staging: chunk s = tid + t*256; row = s>>3 (0..127), c = s&7
    int sws[4];
    size_t goff[4];
#pragma unroll
    for (int t = 0; t < 4; t++) {
        int s = tid + (t << 8);
        int row = s >> 3, c = s & 7;
        sws[t]  = SW128(row * 128 + c * 16);
        goff[t] = (size_t)row * KDIM + c * 8;
    }

    // ldmatrix per-thread bases (validated R3/R4; fp16 rows are 128B too)
    const int xmask = (lane & 7) << 4;
    const int a_b0 = (wm * 64 + (lane & 15)) * 128 + ((lane >> 4) & 1) * 16;
    const int b_b0 = (wn * 32 + (lane & 7) + ((lane >> 4) & 1) * 8) * 128 +
                     ((lane >> 3) & 1) * 16;

    float acc[4][4][4];
#pragma unroll
    for (int i = 0; i < 4; i++)
#pragma unroll
        for (int j = 0; j < 4; j++)
#pragma unroll
            for (int q = 0; q < 4; q++) acc[i][j][q] = 0.f;

    auto stage = [&](int kt, uint32_t base) {
        const int kofs = kt * 64;
#pragma unroll
        for (int t = 0; t < 4; t++) {
            const size_t g = goff[t] + kofs;
            cp16(base + sws[t],        Abh + g);
            cp16(base + A_LO + sws[t], Abl + g);
            cp16(base + B_HI + sws[t], Bbh + g);
        }
    };

    // ---- prologue: fill stages 0,1 ----
    stage(0, smb);         CP_COMMIT();
    stage(1, smb + STAGE); CP_COMMIT();
    CP_WAIT1();            // stage 0 resident
    __syncthreads();

    for (int kt = 0; kt < NK; ++kt) {
        const uint32_t sA = smb + (kt % 3) * STAGE;

        if (kt + 2 < NK) stage(kt + 2, smb + ((kt + 2) % 3) * STAGE);
        CP_COMMIT();  // one group per iter (may be empty at tail)

#pragma unroll
        for (int k16 = 0; k16 < 4; k16++) {
            uint32_t ah[4][4], al[4][4], bh[2][4];
#pragma unroll
            for (int mt = 0; mt < 4; mt++) {
                int off = (a_b0 + mt * 2048 + k16 * 32) ^ xmask;
                ldsm4(ah[mt], sA + off);
                ldsm4(al[mt], sA + A_LO + off);
            }
#pragma unroll
            for (int nt2 = 0; nt2 < 2; nt2++) {
                int off = (b_b0 + nt2 * 2048 + k16 * 32) ^ xmask;
                ldsm4(bh[nt2], sA + B_HI + off);
            }
            // pass 1: ah * bh  (pass-major, RAW distance 16)
#pragma unroll
            for (int mt = 0; mt < 4; mt++)
#pragma unroll
                for (int nt = 0; nt < 4; nt++) {
                    const int g = nt >> 1, s2 = (nt & 1) * 2;
                    mma_f16(acc[mt][nt], ah[mt], bh[g][s2], bh[g][s2 + 1]);
                }
            // pass 2: al * bh  (same accumulators: (ah+al)*bh = a*bh)
#pragma unroll
            for (int mt = 0; mt < 4; mt++)
#pragma unroll
                for (int nt = 0; nt < 4; nt++) {
                    const int g = nt >> 1, s2 = (nt & 1) * 2;
                    mma_f16(acc[mt][nt], al[mt], bh[g][s2], bh[g][s2 + 1]);
                }
        }

        if (kt + 1 < NK) {
            CP_WAIT1();        // stage kt+1 resident (kt+2 in flight)
            __syncthreads();   // frees ring slot kt%3
        }
    }

    // ---- epilogue ----
    const float* bp = bias + (size_t)e * NCOLS + n0 + wn * 32;
    float2 bvv[4];
#pragma unroll
    for (int nt = 0; nt < 4; nt++)
        bvv[nt] = *(const float2*)(bp + nt * 8 + (lane & 3) * 2);

    const size_t rbase = (size_t)e * 1024 + m0 + wm * 64;
#pragma unroll
    for (int mt = 0; mt < 4; mt++) {
        int r = mt * 16 + (lane >> 2);
#pragma unroll
        for (int nt = 0; nt < 4; nt++) {
            int col = n0 + wn * 32 + nt * 8 + (lane & 3) * 2;
            float2 v0, v1;
            v0.x = acc[mt][nt][0] + bvv[nt].x;
            v0.y = acc[mt][nt][1] + bvv[nt].y;
            v1.x = acc[mt][nt][2] + bvv[nt].x;
            v1.y = acc[mt][nt][3] + bvv[nt].y;
            if (RELU) {
                v0.x = fmaxf(v0.x, 0.f); v0.y = fmaxf(v0.y, 0.f);
                v1.x = fmaxf(v1.x, 0.f); v1.y = fmaxf(v1.y, 0.f);
            }
            const size_t i0 = (rbase + r) * NCOLS + col;
            const size_t i1 = (rbase + r + 8) * NCOLS + col;
            if (SPLIT) {
                float h0x = __half2float(__float2half_rn(v0.x));
                float h0y = __half2float(__float2half_rn(v0.y));
                float h1x = __half2float(__float2half_rn(v1.x));
                float h1y = __half2float(__float2half_rn(v1.y));
                *(uint32_t*)(Ch + i0) = pack_h2(h0x, h0y);
                *(uint32_t*)(Cl + i0) = pack_h2(v0.x - h0x, v0.y - h0y);
                *(uint32_t*)(Ch + i1) = pack_h2(h1x, h1y);
                *(uint32_t*)(Cl + i1) = pack_h2(v1.x - h1x, v1.y - h1y);
            } else {
                *(float2*)(Cf + i0) = v0;
                *(float2*)(Cf + i1) = v1;
            }
        }
    }
}

extern "C" void kernel_launch(void* const* d_in, const int* in_sizes, int n_in,
                              void* d_out, int out_size) {
    (void)in_sizes; (void)n_in; (void)out_size;
    const float* xs = (const float*)d_in[0];
    const float* w1 = (const float*)d_in[2];
    const float* b1 = (const float*)d_in[3];
    const float* w2 = (const float*)d_in[4];
    const float* b2 = (const float*)d_in[5];
    float* out = (float*)d_out;

    void *xh, *xl, *w1h, *w2h, *hh, *hl;
    cudaGetSymbolAddress(&xh,  g_xs_h);  cudaGetSymbolAddress(&xl,  g_xs_l);
    cudaGetSymbolAddress(&w1h, g_w1_h);  cudaGetSymbolAddress(&w2h, g_w2_h);
    cudaGetSymbolAddress(&hh,  g_hid_h); cudaGetSymbolAddress(&hl,  g_hid_l);

    cudaFuncSetAttribute(ffn_h2<4096, 1024, true, true>,
                         cudaFuncAttributeMaxDynamicSharedMemorySize, SMEM_TOTAL);
    cudaFuncSetAttribute(ffn_h2<1024, 4096, false, false>,
                         cudaFuncAttributeMaxDynamicSharedMemorySize, SMEM_TOTAL);

    // prepass: xs -> fp16 h/l; w1, w2 -> single fp16
    split_f16_k<<<16384, 256>>>((const float4*)xs, (uint2*)xh, (uint2*)xl,
                                16777216 / 4);
    conv_f16_k<<<65536, 256>>>((const float4*)w1, (uint2*)w1h, 67108864 / 4);
    conv_f16_k<<<65536, 256>>>((const float4*)w2, (uint2*)w2h, 67108864 / 4);

    // GEMM1: bias+relu, hidden written as fp16 h/l planes
    ffn_h2<4096, 1024, true, true><<<dim3(32, 8, 16), 256, SMEM_TOTAL>>>(
        (const __half*)xh, (const __half*)xl, (const __half*)w1h,
        b1, nullptr, (__half*)hh, (__half*)hl);
    // GEMM2: bias, fp32 out
    ffn_h2<1024, 4096, false, false><<<dim3(8, 8, 16), 256, SMEM_TOTAL>>>(
        (const __half*)hh, (const __half*)hl, (const __half*)w2h,
        b2, out, nullptr, nullptr);
}

// round 13
// speedup vs baseline: 6.0942x; 1.5720x over previous
#include <cuda_runtime.h>
#include <cuda_fp16.h>
#include <cstdint>
#include <cstddef>

// E=16, D=1024, H=4096, N=16384 (1024 tokens/expert, contiguous).
// GEMM1: per-expert [1024 x 4096 x 1024], relu(X*W1^T + b1) -> hidden (fp16)
// GEMM2: per-expert [1024 x 1024 x 4096], H*W2^T + b2       -> fp32 out
// R13: SINGLE-pass fp16 mma.sync (both operands fp16, fp32 accumulate).
// Error budget: 4 fp16-rounding units (xs, w1, hidden, w2) ~ 4e-4 << 1e-3.
// Half the HMMA count of R12's 2-pass (R4..R12: time tracks tensor
// instruction count), 2/3 the SMEM/global traffic, smaller prepass.
// Geometry = validated R4 skeleton: BM=128,BN=128,BK=64, 256 thr, SW128,
// cp.async 3-stage ring (2 planes x 16KB = 32KB/stage).

static __device__ __half g_xs_h[16777216];
static __device__ __half g_w1_h[67108864];
static __device__ __half g_w2_h[67108864];
static __device__ __half g_hid_h[67108864];

__device__ __forceinline__ uint32_t smem_u32(const void* p) {
    uint32_t a;
    asm("{ .reg .u64 t; cvta.to.shared.u64 t, %1; cvt.u32.u64 %0, t; }"
        : "=r"(a) : "l"(p));
    return a;
}
#define SW128(x) ((x) ^ (((x) >> 3) & 0x70))

// lower half = fp16(a), upper half = fp16(b)
__device__ __forceinline__ uint32_t pack_h2(float a, float b) {
    uint32_t r;
    asm("cvt.rn.f16x2.f32 %0, %1, %2;" : "=r"(r) : "f"(b), "f"(a));
    return r;
}
__device__ __forceinline__ void ldsm4(uint32_t* r, uint32_t addr) {
    asm volatile("ldmatrix.sync.aligned.m8n8.x4.shared.b16 {%0,%1,%2,%3}, [%4];"
                 : "=r"(r[0]), "=r"(r[1]), "=r"(r[2]), "=r"(r[3]) : "r"(addr));
}
__device__ __forceinline__ void mma_f16(float* c, const uint32_t* a,
                                        uint32_t b0, uint32_t b1) {
    asm volatile(
        "mma.sync.aligned.m16n8k16.row.col.f32.f16.f16.f32 "
        "{%0,%1,%2,%3}, {%4,%5,%6,%7}, {%8,%9}, {%0,%1,%2,%3};"
        : "+f"(c[0]), "+f"(c[1]), "+f"(c[2]), "+f"(c[3])
        : "r"(a[0]), "r"(a[1]), "r"(a[2]), "r"(a[3]), "r"(b0), "r"(b1));
}
__device__ __forceinline__ void cp16(uint32_t dst, const void* src) {
    asm volatile("cp.async.cg.shared.global [%0], [%1], 16;"
                 :: "r"(dst), "l"(src) : "memory");
}
#define CP_COMMIT() asm volatile("cp.async.commit_group;" ::: "memory")
#define CP_WAIT1()  asm volatile("cp.async.wait_group 1;" ::: "memory")

// -------- fp32 -> fp16 convert --------
__global__ __launch_bounds__(256)
void conv_f16_k(const float4* __restrict__ in, uint2* __restrict__ out, int n4) {
    int i = blockIdx.x * 256 + threadIdx.x;
    if (i >= n4) return;
    float4 f = in[i];
    out[i] = make_uint2(pack_h2(f.x, f.y), pack_h2(f.z, f.w));
}

// SMEM stage (fp16, 64-elem rows = 128B, SW128):
//   A @0 (16KB)  B @16384  -> 32KB/stage, 3 stages
static constexpr int B_OFF = 16384;
static constexpr int STAGE = 32768;
static constexpr int SMEM_TOTAL = 3 * STAGE;  // 96 KB

template <int NCOLS, int KDIM, bool RELU, bool HALF_OUT>
__global__ __launch_bounds__(256, 1)
void ffn_h1(const __half* __restrict__ A, const __half* __restrict__ B,
            const float* __restrict__ bias,
            float* __restrict__ Cf, __half* __restrict__ Ch)
{
    constexpr int NK = KDIM / 64;
    extern __shared__ char smem[];
    const uint32_t smb = smem_u32(smem);

    const int tid  = threadIdx.x;
    const int lane = tid & 31, warp = tid >> 5;
    const int wm = warp >> 2, wn = warp & 3;  // 2x4, warp tile 64(M) x 32(N)
    const int e  = blockIdx.z;
    const int m0 = blockIdx.y * 128, n0 = blockIdx.x * 128;

    const __half* Ab = A + ((size_t)e * 1024 + m0) * KDIM;
    const __half* Bb = B + ((size_t)e * NCOLS + n0) * KDIM;

    // staging: chunk s = tid + t*256; row = s>>3 (0..127), c = s&7
    int sws[4];
    size_t goff[4];
#pragma unroll
    for (int t = 0; t < 4; t++) {
        int s = tid + (t << 8);
        int row = s >> 3, c = s & 7;
        sws[t]  = SW128(row * 128 + c * 16);
        goff[t] = (size_t)row * KDIM + c * 8;
    }

    // ldmatrix per-thread bases (validated R3..R12)
    const int xmask = (lane & 7) << 4;
    const int a_b0 = (wm * 64 + (lane & 15)) * 128 + ((lane >> 4) & 1) * 16;
    const int b_b0 = (wn * 32 + (lane & 7) + ((lane >> 4) & 1) * 8) * 128 +
                     ((lane >> 3) & 1) * 16;

    float acc[4][4][4];
#pragma unroll
    for (int i = 0; i < 4; i++)
#pragma unroll
        for (int j = 0; j < 4; j++)
#pragma unroll
            for (int q = 0; q < 4; q++) acc[i][j][q] = 0.f;

    auto stage = [&](int kt, uint32_t base) {
        const int kofs = kt * 64;
#pragma unroll
        for (int t = 0; t < 4; t++) {
            const size_t g = goff[t] + kofs;
            cp16(base + sws[t],         Ab + g);
            cp16(base + B_OFF + sws[t], Bb + g);
        }
    };

    // ---- prologue: fill stages 0,1 ----
    stage(0, smb);         CP_COMMIT();
    stage(1, smb + STAGE); CP_COMMIT();
    CP_WAIT1();            // stage 0 resident
    __syncthreads();

    for (int kt = 0; kt < NK; ++kt) {
        const uint32_t sA = smb + (kt % 3) * STAGE;

        if (kt + 2 < NK) stage(kt + 2, smb + ((kt + 2) % 3) * STAGE);
        CP_COMMIT();  // one group per iter (may be empty at tail)

#pragma unroll
        for (int k16 = 0; k16 < 4; k16++) {
            uint32_t ah[4][4], bh[2][4];
#pragma unroll
            for (int mt = 0; mt < 4; mt++) {
                int off = (a_b0 + mt * 2048 + k16 * 32) ^ xmask;
                ldsm4(ah[mt], sA + off);
            }
#pragma unroll
            for (int nt2 = 0; nt2 < 2; nt2++) {
                int off = (b_b0 + nt2 * 2048 + k16 * 32) ^ xmask;
                ldsm4(bh[nt2], sA + B_OFF + off);
            }
#pragma unroll
            for (int mt = 0; mt < 4; mt++)
#pragma unroll
                for (int nt = 0; nt < 4; nt++) {
                    const int g = nt >> 1, s2 = (nt & 1) * 2;
                    mma_f16(acc[mt][nt], ah[mt], bh[g][s2], bh[g][s2 + 1]);
                }
        }

        if (kt + 1 < NK) {
            CP_WAIT1();        // stage kt+1 resident (kt+2 in flight)
            __syncthreads();   // frees ring slot kt%3
        }
    }

    // ---- epilogue ----
    const float* bp = bias + (size_t)e * NCOLS + n0 + wn * 32;
    float2 bvv[4];
#pragma unroll
    for (int nt = 0; nt < 4; nt++)
        bvv[nt] = *(const float2*)(bp + nt * 8 + (lane & 3) * 2);

    const size_t rbase = (size_t)e * 1024 + m0 + wm * 64;
#pragma unroll
    for (int mt = 0; mt < 4; mt++) {
        int r = mt * 16 + (lane >> 2);
#pragma unroll
        for (int nt = 0; nt < 4; nt++) {
            int col = n0 + wn * 32 + nt * 8 + (lane & 3) * 2;
            float2 v0, v1;
            v0.x = acc[mt][nt][0] + bvv[nt].x;
            v0.y = acc[mt][nt][1] + bvv[nt].y;
            v1.x = acc[mt][nt][2] + bvv[nt].x;
            v1.y = acc[mt][nt][3] + bvv[nt].y;
            if (RELU) {
                v0.x = fmaxf(v0.x, 0.f); v0.y = fmaxf(v0.y, 0.f);
                v1.x = fmaxf(v1.x, 0.f); v1.y = fmaxf(v1.y, 0.f);
            }
            const size_t i0 = (rbase + r) * NCOLS + col;
            const size_t i1 = (rbase + r + 8) * NCOLS + col;
            if (HALF_OUT) {
                *(uint32_t*)(Ch + i0) = pack_h2(v0.x, v0.y);
                *(uint32_t*)(Ch + i1) = pack_h2(v1.x, v1.y);
            } else {
                *(float2*)(Cf + i0) = v0;
                *(float2*)(Cf + i1) = v1;
            }
        }
    }
}

extern "C" void kernel_launch(void* const* d_in, const int* in_sizes, int n_in,
                              void* d_out, int out_size) {
    (void)in_sizes; (void)n_in; (void)out_size;
    const float* xs = (const float*)d_in[0];
    const float* w1 = (const float*)d_in[2];
    const float* b1 = (const float*)d_in[3];
    const float* w2 = (const float*)d_in[4];
    const float* b2 = (const float*)d_in[5];
    float* out = (float*)d_out;

    void *xh, *w1h, *w2h, *hh;
    cudaGetSymbolAddress(&xh,  g_xs_h);
    cudaGetSymbolAddress(&w1h, g_w1_h);
    cudaGetSymbolAddress(&w2h, g_w2_h);
    cudaGetSymbolAddress(&hh,  g_hid_h);

    cudaFuncSetAttribute(ffn_h1<4096, 1024, true, true>,
                         cudaFuncAttributeMaxDynamicSharedMemorySize, SMEM_TOTAL);
    cudaFuncSetAttribute(ffn_h1<1024, 4096, false, false>,
                         cudaFuncAttributeMaxDynamicSharedMemorySize, SMEM_TOTAL);

    // prepass: everything to single fp16 planes
    conv_f16_k<<<16384, 256>>>((const float4*)xs, (uint2*)xh, 16777216 / 4);
    conv_f16_k<<<65536, 256>>>((const float4*)w1, (uint2*)w1h, 67108864 / 4);
    conv_f16_k<<<65536, 256>>>((const float4*)w2, (uint2*)w2h, 67108864 / 4);

    // GEMM1: bias+relu, hidden written as fp16
    ffn_h1<4096, 1024, true, true><<<dim3(32, 8, 16), 256, SMEM_TOTAL>>>(
        (const __half*)xh, (const __half*)w1h, b1, nullptr, (__half*)hh);
    // GEMM2: bias, fp32 out
    ffn_h1<1024, 4096, false, false><<<dim3(8, 8, 16), 256, SMEM_TOTAL>>>(
        (const __half*)hh, (const __half*)w2h, b2, out, nullptr);
}

// round 14
// speedup vs baseline: 6.5474x; 1.0744x over previous
#include <cuda_runtime.h>
#include <cuda_fp16.h>
#include <cstdint>
#include <cstddef>

// E=16, D=1024, H=4096, N=16384 (1024 tokens/expert, contiguous).
// GEMM1: per-expert [1024 x 4096 x 1024], relu(X*W1^T + b1) -> hidden (fp16)
// GEMM2: per-expert [1024 x 1024 x 4096], H*W2^T + b2       -> fp32 out
// R14 = R13 single-pass fp16 math + R9 big-tile geometry:
//   CTA 128x256, 8 warps (2x4), warp tile 64x64 -> 8 ldsm per 32 MMA (0.25
//   vs R13's 0.375), doubling the MMA duty cycle that capped R13 at 54.5%
//   tensor. 1-pass frag count (32 regs) keeps total ~215 regs (R9's 255-reg
//   failure was 3-pass frags). 3-stage cp.async ring (48KB/stage = 144KB).

static __device__ __half g_xs_h[16777216];
static __device__ __half g_w1_h[67108864];
static __device__ __half g_w2_h[67108864];
static __device__ __half g_hid_h[67108864];

__device__ __forceinline__ uint32_t smem_u32(const void* p) {
    uint32_t a;
    asm("{ .reg .u64 t; cvta.to.shared.u64 t, %1; cvt.u32.u64 %0, t; }"
        : "=r"(a) : "l"(p));
    return a;
}
#define SW128(x) ((x) ^ (((x) >> 3) & 0x70))

// lower half = fp16(a), upper half = fp16(b)
__device__ __forceinline__ uint32_t pack_h2(float a, float b) {
    uint32_t r;
    asm("cvt.rn.f16x2.f32 %0, %1, %2;" : "=r"(r) : "f"(b), "f"(a));
    return r;
}
__device__ __forceinline__ void ldsm4(uint32_t* r, uint32_t addr) {
    asm volatile("ldmatrix.sync.aligned.m8n8.x4.shared.b16 {%0,%1,%2,%3}, [%4];"
                 : "=r"(r[0]), "=r"(r[1]), "=r"(r[2]), "=r"(r[3]) : "r"(addr));
}
__device__ __forceinline__ void mma_f16(float* c, const uint32_t* a,
                                        uint32_t b0, uint32_t b1) {
    asm volatile(
        "mma.sync.aligned.m16n8k16.row.col.f32.f16.f16.f32 "
        "{%0,%1,%2,%3}, {%4,%5,%6,%7}, {%8,%9}, {%0,%1,%2,%3};"
        : "+f"(c[0]), "+f"(c[1]), "+f"(c[2]), "+f"(c[3])
        : "r"(a[0]), "r"(a[1]), "r"(a[2]), "r"(a[3]), "r"(b0), "r"(b1));
}
__device__ __forceinline__ void cp16(uint32_t dst, const void* src) {
    asm volatile("cp.async.cg.shared.global [%0], [%1], 16;"
                 :: "r"(dst), "l"(src) : "memory");
}
#define CP_COMMIT() asm volatile("cp.async.commit_group;" ::: "memory")
#define CP_WAIT1()  asm volatile("cp.async.wait_group 1;" ::: "memory")

// -------- fp32 -> fp16 convert --------
__global__ __launch_bounds__(256)
void conv_f16_k(const float4* __restrict__ in, uint2* __restrict__ out, int n4) {
    int i = blockIdx.x * 256 + threadIdx.x;
    if (i >= n4) return;
    float4 f = in[i];
    out[i] = make_uint2(pack_h2(f.x, f.y), pack_h2(f.z, f.w));
}

// SMEM stage (fp16, 64-elem rows = 128B, SW128):
//   A @0 (16KB, 128 rows)  B @16384 (32KB, 256 rows)  -> 48KB/stage, 3 stages
static constexpr int B_OFF = 16384;
static constexpr int STAGE = 49152;
static constexpr int SMEM_TOTAL = 3 * STAGE;  // 144 KB

template <int NCOLS, int KDIM, bool RELU, bool HALF_OUT>
__global__ __launch_bounds__(256, 1)
void ffn_h3(const __half* __restrict__ A, const __half* __restrict__ B,
            const float* __restrict__ bias,
            float* __restrict__ Cf, __half* __restrict__ Ch)
{
    constexpr int NK = KDIM / 64;
    extern __shared__ char smem[];
    const uint32_t smb = smem_u32(smem);

    const int tid  = threadIdx.x;
    const int lane = tid & 31, warp = tid >> 5;
    const int wm = warp >> 2, wn = warp & 3;  // 2x4, warp tile 64(M) x 64(N)
    const int e  = blockIdx.z;
    const int m0 = blockIdx.y * 128, n0 = blockIdx.x * 256;

    const __half* Ab = A + ((size_t)e * 1024 + m0) * KDIM;
    const __half* Bb = B + ((size_t)e * NCOLS + n0) * KDIM;

    // ldmatrix per-thread bases (A validated R4; B 64-col version validated R9)
    const int xmask = (lane & 7) << 4;
    const int a_b0 = (wm * 64 + (lane & 15)) * 128 + ((lane >> 4) & 1) * 16;
    const int b_b0 = (wn * 64 + (lane & 7) + ((lane >> 4) & 1) * 8) * 128 +
                     ((lane >> 3) & 1) * 16;

    float acc[4][8][4];
#pragma unroll
    for (int i = 0; i < 4; i++)
#pragma unroll
        for (int j = 0; j < 8; j++)
#pragma unroll
            for (int q = 0; q < 4; q++) acc[i][j][q] = 0.f;

    // staging (recompute addresses to hold reg pressure down):
    // A: 1024 16B-chunks (4/thread); B: 2048 (8/thread)
    auto stage = [&](int kt, uint32_t base) {
        const int kofs = kt * 64;
#pragma unroll
        for (int t = 0; t < 4; t++) {
            int s = tid + (t << 8);
            int row = s >> 3, c = s & 7;
            int sw = SW128(row * 128 + c * 16);
            cp16(base + sw, Ab + (size_t)row * KDIM + kofs + c * 8);
        }
#pragma unroll
        for (int t = 0; t < 8; t++) {
            int s = tid + (t << 8);
            int row = s >> 3, c = s & 7;
            int sw = SW128(row * 128 + c * 16);
            cp16(base + B_OFF + sw, Bb + (size_t)row * KDIM + kofs + c * 8);
        }
    };

    // ---- prologue: fill stages 0,1 ----
    stage(0, smb);         CP_COMMIT();
    stage(1, smb + STAGE); CP_COMMIT();
    CP_WAIT1();            // stage 0 resident
    __syncthreads();

    for (int kt = 0; kt < NK; ++kt) {
        const uint32_t sA = smb + (kt % 3) * STAGE;

        if (kt + 2 < NK) stage(kt + 2, smb + ((kt + 2) % 3) * STAGE);
        CP_COMMIT();  // one group per iter (may be empty at tail)

#pragma unroll
        for (int k16 = 0; k16 < 4; k16++) {
            uint32_t ah[4][4], bh[4][4];
#pragma unroll
            for (int mt = 0; mt < 4; mt++) {
                int off = (a_b0 + mt * 2048 + k16 * 32) ^ xmask;
                ldsm4(ah[mt], sA + off);
            }
#pragma unroll
            for (int nt2 = 0; nt2 < 4; nt2++) {
                int off = (b_b0 + nt2 * 2048 + k16 * 32) ^ xmask;
                ldsm4(bh[nt2], sA + B_OFF + off);
            }
#pragma unroll
            for (int mt = 0; mt < 4; mt++)
#pragma unroll
                for (int nt = 0; nt < 8; nt++) {
                    const int g = nt >> 1, s2 = (nt & 1) * 2;
                    mma_f16(acc[mt][nt], ah[mt], bh[g][s2], bh[g][s2 + 1]);
                }
        }

        if (kt + 1 < NK) {
            CP_WAIT1();        // stage kt+1 resident (kt+2 in flight)
            __syncthreads();   // frees ring slot kt%3
        }
    }

    // ---- epilogue ----
    const float* bp = bias + (size_t)e * NCOLS + n0 + wn * 64;
    float2 bvv[8];
#pragma unroll
    for (int nt = 0; nt < 8; nt++)
        bvv[nt] = *(const float2*)(bp + nt * 8 + (lane & 3) * 2);

    const size_t rbase = (size_t)e * 1024 + m0 + wm * 64;
#pragma unroll
    for (int mt = 0; mt < 4; mt++) {
        int r = mt * 16 + (lane >> 2);
#pragma unroll
        for (int nt = 0; nt < 8; nt++) {
            int col = n0 + wn * 64 + nt * 8 + (lane & 3) * 2;
            float2 v0, v1;
            v0.x = acc[mt][nt][0] + bvv[nt].x;
            v0.y = acc[mt][nt][1] + bvv[nt].y;
            v1.x = acc[mt][nt][2] + bvv[nt].x;
            v1.y = acc[mt][nt][3] + bvv[nt].y;
            if (RELU) {
                v0.x = fmaxf(v0.x, 0.f); v0.y = fmaxf(v0.y, 0.f);
                v1.x = fmaxf(v1.x, 0.f); v1.y = fmaxf(v1.y, 0.f);
            }
            const size_t i0 = (rbase + r) * NCOLS + col;
            const size_t i1 = (rbase + r + 8) * NCOLS + col;
            if (HALF_OUT) {
                *(uint32_t*)(Ch + i0) = pack_h2(v0.x, v0.y);
                *(uint32_t*)(Ch + i1) = pack_h2(v1.x, v1.y);
            } else {
                *(float2*)(Cf + i0) = v0;
                *(float2*)(Cf + i1) = v1;
            }
        }
    }
}

extern "C" void kernel_launch(void* const* d_in, const int* in_sizes, int n_in,
                              void* d_out, int out_size) {
    (void)in_sizes; (void)n_in; (void)out_size;
    const float* xs = (const float*)d_in[0];
    const float* w1 = (const float*)d_in[2];
    const float* b1 = (const float*)d_in[3];
    const float* w2 = (const float*)d_in[4];
    const float* b2 = (const float*)d_in[5];
    float* out = (float*)d_out;

    void *xh, *w1h, *w2h, *hh;
    cudaGetSymbolAddress(&xh,  g_xs_h);
    cudaGetSymbolAddress(&w1h, g_w1_h);
    cudaGetSymbolAddress(&w2h, g_w2_h);
    cudaGetSymbolAddress(&hh,  g_hid_h);

    cudaFuncSetAttribute(ffn_h3<4096, 1024, true, true>,
                         cudaFuncAttributeMaxDynamicSharedMemorySize, SMEM_TOTAL);
    cudaFuncSetAttribute(ffn_h3<1024, 4096, false, false>,
                         cudaFuncAttributeMaxDynamicSharedMemorySize, SMEM_TOTAL);

    // prepass: everything to single fp16 planes
    conv_f16_k<<<16384, 256>>>((const float4*)xs, (uint2*)xh, 16777216 / 4);
    conv_f16_k<<<65536, 256>>>((const float4*)w1, (uint2*)w1h, 67108864 / 4);
    conv_f16_k<<<65536, 256>>>((const float4*)w2, (uint2*)w2h, 67108864 / 4);

    // GEMM1: bias+relu, hidden written as fp16 (N=4096 -> 16 n-blocks)
    ffn_h3<4096, 1024, true, true><<<dim3(16, 8, 16), 256, SMEM_TOTAL>>>(
        (const __half*)xh, (const __half*)w1h, b1, nullptr, (__half*)hh);
    // GEMM2: bias, fp32 out (N=1024 -> 4 n-blocks)
    ffn_h3<1024, 4096, false, false><<<dim3(4, 8, 16), 256, SMEM_TOTAL>>>(
        (const __half*)hh, (const __half*)w2h, b2, out, nullptr);
}

// round 15
// speedup vs baseline: 6.5779x; 1.0047x over previous
#include <cuda_runtime.h>
#include <cuda_fp16.h>
#include <cstdint>
#include <cstddef>

// E=16, D=1024, H=4096, N=16384 (1024 tokens/expert, contiguous).
// GEMM1: per-expert [1024 x 4096 x 1024], relu(X*W1^T + b1) -> hidden (fp16)
// GEMM2: per-expert [1024 x 1024 x 4096], H*W2^T + b2       -> fp32 out
// R15 = R14 (1-pass fp16, CTA 128x256, warp tile 64x64, 3-stage ring) +
//  (a) A-ldsm interleaved into the MMA stream (B frags first, ah[mt+1] loads
//      hidden under mt's 8 MMAs) -- removes the serialized 8-ldsm batch that
//      left ~60 exposed cycles per k16 and capped tensor at 63.8%;
//  (b) single merged fp32->fp16 convert kernel for xs/w1/w2 (one launch).

static __device__ __half g_xs_h[16777216];
static __device__ __half g_w1_h[67108864];
static __device__ __half g_w2_h[67108864];
static __device__ __half g_hid_h[67108864];

__device__ __forceinline__ uint32_t smem_u32(const void* p) {
    uint32_t a;
    asm("{ .reg .u64 t; cvta.to.shared.u64 t, %1; cvt.u32.u64 %0, t; }"
        : "=r"(a) : "l"(p));
    return a;
}
#define SW128(x) ((x) ^ (((x) >> 3) & 0x70))

// lower half = fp16(a), upper half = fp16(b)
__device__ __forceinline__ uint32_t pack_h2(float a, float b) {
    uint32_t r;
    asm("cvt.rn.f16x2.f32 %0, %1, %2;" : "=r"(r) : "f"(b), "f"(a));
    return r;
}
__device__ __forceinline__ void ldsm4(uint32_t* r, uint32_t addr) {
    asm volatile("ldmatrix.sync.aligned.m8n8.x4.shared.b16 {%0,%1,%2,%3}, [%4];"
                 : "=r"(r[0]), "=r"(r[1]), "=r"(r[2]), "=r"(r[3]) : "r"(addr));
}
__device__ __forceinline__ void mma_f16(float* c, const uint32_t* a,
                                        uint32_t b0, uint32_t b1) {
    asm volatile(
        "mma.sync.aligned.m16n8k16.row.col.f32.f16.f16.f32 "
        "{%0,%1,%2,%3}, {%4,%5,%6,%7}, {%8,%9}, {%0,%1,%2,%3};"
        : "+f"(c[0]), "+f"(c[1]), "+f"(c[2]), "+f"(c[3])
        : "r"(a[0]), "r"(a[1]), "r"(a[2]), "r"(a[3]), "r"(b0), "r"(b1));
}
__device__ __forceinline__ void cp16(uint32_t dst, const void* src) {
    asm volatile("cp.async.cg.shared.global [%0], [%1], 16;"
                 :: "r"(dst), "l"(src) : "memory");
}
#define CP_COMMIT() asm volatile("cp.async.commit_group;" ::: "memory")
#define CP_WAIT1()  asm volatile("cp.async.wait_group 1;" ::: "memory")

// -------- merged fp32 -> fp16 convert for xs, w1, w2 (one launch) --------
// n4 sizes: xs 4194304, w1 16777216, w2 16777216 quads (total 37748736).
__global__ __launch_bounds__(256)
void conv_all_k(const float4* __restrict__ xs, uint2* __restrict__ xo,
                const float4* __restrict__ w1, uint2* __restrict__ w1o,
                const float4* __restrict__ w2, uint2* __restrict__ w2o) {
    int i = blockIdx.x * 256 + threadIdx.x;
    const float4* in;
    uint2* out;
    if (i < 4194304)        { in = xs;  out = xo;  }
    else if (i < 20971520)  { in = w1;  out = w1o; i -= 4194304; }
    else                    { in = w2;  out = w2o; i -= 20971520; }
    float4 f = in[i];
    out[i] = make_uint2(pack_h2(f.x, f.y), pack_h2(f.z, f.w));
}

// SMEM stage (fp16, 64-elem rows = 128B, SW128):
//   A @0 (16KB, 128 rows)  B @16384 (32KB, 256 rows)  -> 48KB/stage, 3 stages
static constexpr int B_OFF = 16384;
static constexpr int STAGE = 49152;
static constexpr int SMEM_TOTAL = 3 * STAGE;  // 144 KB

template <int NCOLS, int KDIM, bool RELU, bool HALF_OUT>
__global__ __launch_bounds__(256, 1)
void ffn_h4(const __half* __restrict__ A, const __half* __restrict__ B,
            const float* __restrict__ bias,
            float* __restrict__ Cf, __half* __restrict__ Ch)
{
    constexpr int NK = KDIM / 64;
    extern __shared__ char smem[];
    const uint32_t smb = smem_u32(smem);

    const int tid  = threadIdx.x;
    const int lane = tid & 31, warp = tid >> 5;
    const int wm = warp >> 2, wn = warp & 3;  // 2x4, warp tile 64(M) x 64(N)
    const int e  = blockIdx.z;
    const int m0 = blockIdx.y * 128, n0 = blockIdx.x * 256;

    const __half* Ab = A + ((size_t)e * 1024 + m0) * KDIM;
    const __half* Bb = B + ((size_t)e * NCOLS + n0) * KDIM;

    // ldmatrix per-thread bases (A validated R4; B 64-col validated R9/R14)
    const int xmask = (lane & 7) << 4;
    const int a_b0 = (wm * 64 + (lane & 15)) * 128 + ((lane >> 4) & 1) * 16;
    const int b_b0 = (wn * 64 + (lane & 7) + ((lane >> 4) & 1) * 8) * 128 +
                     ((lane >> 3) & 1) * 16;

    float acc[4][8][4];
#pragma unroll
    for (int i = 0; i < 4; i++)
#pragma unroll
        for (int j = 0; j < 8; j++)
#pragma unroll
            for (int q = 0; q < 4; q++) acc[i][j][q] = 0.f;

    // staging (addresses recomputed; ALU is cheap relative to tensor)
    auto stage = [&](int kt, uint32_t base) {
        const int kofs = kt * 64;
#pragma unroll
        for (int t = 0; t < 4; t++) {
            int s = tid + (t << 8);
            int row = s >> 3, c = s & 7;
            int sw = SW128(row * 128 + c * 16);
            cp16(base + sw, Ab + (size_t)row * KDIM + kofs + c * 8);
        }
#pragma unroll
        for (int t = 0; t < 8; t++) {
            int s = tid + (t << 8);
            int row = s >> 3, c = s & 7;
            int sw = SW128(row * 128 + c * 16);
            cp16(base + B_OFF + sw, Bb + (size_t)row * KDIM + kofs + c * 8);
        }
    };

    // ---- prologue: fill stages 0,1 ----
    stage(0, smb);         CP_COMMIT();
    stage(1, smb + STAGE); CP_COMMIT();
    CP_WAIT1();            // stage 0 resident
    __syncthreads();

    for (int kt = 0; kt < NK; ++kt) {
        const uint32_t sA = smb + (kt % 3) * STAGE;

        if (kt + 2 < NK) stage(kt + 2, smb + ((kt + 2) % 3) * STAGE);
        CP_COMMIT();  // one group per iter (may be empty at tail)

#pragma unroll
        for (int k16 = 0; k16 < 4; k16++) {
            uint32_t ah[4][4], bh[4][4];
            // B frags first (they gate every MMA column group)
#pragma unroll
            for (int nt2 = 0; nt2 < 4; nt2++) {
                int off = (b_b0 + nt2 * 2048 + k16 * 32) ^ xmask;
                ldsm4(bh[nt2], sA + B_OFF + off);
            }
            // first A row-block
            ldsm4(ah[0], sA + ((a_b0 + k16 * 32) ^ xmask));
            // interleave: load ah[mt+1] ahead of mt's MMA burst so the LDS
            // latency hides under ~56 tensor-busy cycles.
#pragma unroll
            for (int mt = 0; mt < 4; mt++) {
                if (mt < 3) {
                    int off = (a_b0 + (mt + 1) * 2048 + k16 * 32) ^ xmask;
                    ldsm4(ah[mt + 1], sA + off);
                }
#pragma unroll
                for (int nt = 0; nt < 8; nt++) {
                    const int g = nt >> 1, s2 = (nt & 1) * 2;
                    mma_f16(acc[mt][nt], ah[mt], bh[g][s2], bh[g][s2 + 1]);
                }
            }
        }

        if (kt + 1 < NK) {
            CP_WAIT1();        // stage kt+1 resident (kt+2 in flight)
            __syncthreads();   // frees ring slot kt%3
        }
    }

    // ---- epilogue ----
    const float* bp = bias + (size_t)e * NCOLS + n0 + wn * 64;
    float2 bvv[8];
#pragma unroll
    for (int nt = 0; nt < 8; nt++)
        bvv[nt] = *(const float2*)(bp + nt * 8 + (lane & 3) * 2);

    const size_t rbase = (size_t)e * 1024 + m0 + wm * 64;
#pragma unroll
    for (int mt = 0; mt < 4; mt++) {
        int r = mt * 16 + (lane >> 2);
#pragma unroll
        for (int nt = 0; nt < 8; nt++) {
            int col = n0 + wn * 64 + nt * 8 + (lane & 3) * 2;
            float2 v0, v1;
            v0.x = acc[mt][nt][0] + bvv[nt].x;
            v0.y = acc[mt][nt][1] + bvv[nt].y;
            v1.x = acc[mt][nt][2] + bvv[nt].x;
            v1.y = acc[mt][nt][3] + bvv[nt].y;
            if (RELU) {
                v0.x = fmaxf(v0.x, 0.f); v0.y = fmaxf(v0.y, 0.f);
                v1.x = fmaxf(v1.x, 0.f); v1.y = fmaxf(v1.y, 0.f);
            }
            const size_t i0 = (rbase + r) * NCOLS + col;
            const size_t i1 = (rbase + r + 8) * NCOLS + col;
            if (HALF_OUT) {
                *(uint32_t*)(Ch + i0) = pack_h2(v0.x, v0.y);
                *(uint32_t*)(Ch + i1) = pack_h2(v1.x, v1.y);
            } else {
                *(float2*)(Cf + i0) = v0;
                *(float2*)(Cf + i1) = v1;
            }
        }
    }
}

extern "C" void kernel_launch(void* const* d_in, const int* in_sizes, int n_in,
                              void* d_out, int out_size) {
    (void)in_sizes; (void)n_in; (void)out_size;
    const float* xs = (const float*)d_in[0];
    const float* w1 = (const float*)d_in[2];
    const float* b1 = (const float*)d_in[3];
    const float* w2 = (const float*)d_in[4];
    const float* b2 = (const float*)d_in[5];
    float* out = (float*)d_out;

    void *xh, *w1h, *w2h, *hh;
    cudaGetSymbolAddress(&xh,  g_xs_h);
    cudaGetSymbolAddress(&w1h, g_w1_h);
    cudaGetSymbolAddress(&w2h, g_w2_h);
    cudaGetSymbolAddress(&hh,  g_hid_h);

    cudaFuncSetAttribute(ffn_h4<4096, 1024, true, true>,
                         cudaFuncAttributeMaxDynamicSharedMemorySize, SMEM_TOTAL);
    cudaFuncSetAttribute(ffn_h4<1024, 4096, false, false>,
                         cudaFuncAttributeMaxDynamicSharedMemorySize, SMEM_TOTAL);

    // merged prepass: xs, w1, w2 -> fp16 in one launch
    conv_all_k<<<147456, 256>>>((const float4*)xs, (uint2*)xh,
                                (const float4*)w1, (uint2*)w1h,
                                (const float4*)w2, (uint2*)w2h);

    // GEMM1: bias+relu, hidden written as fp16 (N=4096 -> 16 n-blocks)
    ffn_h4<4096, 1024, true, true><<<dim3(16, 8, 16), 256, SMEM_TOTAL>>>(
        (const __half*)xh, (const __half*)w1h, b1, nullptr, (__half*)hh);
    // GEMM2: bias, fp32 out (N=1024 -> 4 n-blocks)
    ffn_h4<1024, 4096, false, false><<<dim3(4, 8, 16), 256, SMEM_TOTAL>>>(
        (const __half*)hh, (const __half*)w2h, b2, out, nullptr);
}

// round 16
// speedup vs baseline: 7.2208x; 1.0977x over previous
#include <cuda_runtime.h>
#include <cuda_fp16.h>
#include <cstdint>
#include <cstddef>

// E=16, D=1024, H=4096, N=16384 (1024 tokens/expert, contiguous).
// GEMM1: per-expert [1024 x 4096 x 1024], relu(X*W1^T + b1) -> hidden (fp16)
// GEMM2: per-expert [1024 x 1024 x 4096], H*W2^T + b2       -> fp32 out
// R16: 1-pass fp16 (R13 math), warp tile 64x64 (R14 ratio), but CTA = 128
// threads / 4 warps (2x2), tile 128x128, 3x32KB ring = 96KB -> 2 CTAs/SM.
// Same 8 warps/SM and identical per-SM MMA work as R14, but the two CTAs
// have independent barriers -> LDSM/barrier/epilogue bubbles decorrelate
// instead of stalling both SMSP warps in phase (the R14/R15 63.8% cap).

static __device__ __half g_xs_h[16777216];
static __device__ __half g_w1_h[67108864];
static __device__ __half g_w2_h[67108864];
static __device__ __half g_hid_h[67108864];

__device__ __forceinline__ uint32_t smem_u32(const void* p) {
    uint32_t a;
    asm("{ .reg .u64 t; cvta.to.shared.u64 t, %1; cvt.u32.u64 %0, t; }"
        : "=r"(a) : "l"(p));
    return a;
}
#define SW128(x) ((x) ^ (((x) >> 3) & 0x70))

// lower half = fp16(a), upper half = fp16(b)
__device__ __forceinline__ uint32_t pack_h2(float a, float b) {
    uint32_t r;
    asm("cvt.rn.f16x2.f32 %0, %1, %2;" : "=r"(r) : "f"(b), "f"(a));
    return r;
}
__device__ __forceinline__ void ldsm4(uint32_t* r, uint32_t addr) {
    asm volatile("ldmatrix.sync.aligned.m8n8.x4.shared.b16 {%0,%1,%2,%3}, [%4];"
                 : "=r"(r[0]), "=r"(r[1]), "=r"(r[2]), "=r"(r[3]) : "r"(addr));
}
__device__ __forceinline__ void mma_f16(float* c, const uint32_t* a,
                                        uint32_t b0, uint32_t b1) {
    asm volatile(
        "mma.sync.aligned.m16n8k16.row.col.f32.f16.f16.f32 "
        "{%0,%1,%2,%3}, {%4,%5,%6,%7}, {%8,%9}, {%0,%1,%2,%3};"
        : "+f"(c[0]), "+f"(c[1]), "+f"(c[2]), "+f"(c[3])
        : "r"(a[0]), "r"(a[1]), "r"(a[2]), "r"(a[3]), "r"(b0), "r"(b1));
}
__device__ __forceinline__ void cp16(uint32_t dst, const void* src) {
    asm volatile("cp.async.cg.shared.global [%0], [%1], 16;"
                 :: "r"(dst), "l"(src) : "memory");
}
#define CP_COMMIT() asm volatile("cp.async.commit_group;" ::: "memory")
#define CP_WAIT1()  asm volatile("cp.async.wait_group 1;" ::: "memory")

// -------- merged fp32 -> fp16 convert for xs, w1, w2 (one launch) --------
__global__ __launch_bounds__(256)
void conv_all_k(const float4* __restrict__ xs, uint2* __restrict__ xo,
                const float4* __restrict__ w1, uint2* __restrict__ w1o,
                const float4* __restrict__ w2, uint2* __restrict__ w2o) {
    int i = blockIdx.x * 256 + threadIdx.x;
    const float4* in;
    uint2* out;
    if (i < 4194304)        { in = xs;  out = xo;  }
    else if (i < 20971520)  { in = w1;  out = w1o; i -= 4194304; }
    else                    { in = w2;  out = w2o; i -= 20971520; }
    float4 f = in[i];
    out[i] = make_uint2(pack_h2(f.x, f.y), pack_h2(f.z, f.w));
}

// SMEM stage (fp16, 64-elem rows = 128B, SW128):
//   A @0 (16KB, 128 rows)  B @16384 (16KB, 128 rows)  -> 32KB/stage, 3 stages
static constexpr int B_OFF = 16384;
static constexpr int STAGE = 32768;
static constexpr int SMEM_TOTAL = 3 * STAGE;  // 96 KB -> 2 CTAs/SM

template <int NCOLS, int KDIM, bool RELU, bool HALF_OUT>
__global__ __launch_bounds__(128, 2)
void ffn_h5(const __half* __restrict__ A, const __half* __restrict__ B,
            const float* __restrict__ bias,
            float* __restrict__ Cf, __half* __restrict__ Ch)
{
    constexpr int NK = KDIM / 64;
    extern __shared__ char smem[];
    const uint32_t smb = smem_u32(smem);

    const int tid  = threadIdx.x;
    const int lane = tid & 31, warp = tid >> 5;   // 4 warps
    const int wm = warp >> 1, wn = warp & 1;      // 2x2, warp tile 64(M) x 64(N)
    const int e  = blockIdx.z;
    const int m0 = blockIdx.y * 128, n0 = blockIdx.x * 128;

    const __half* Ab = A + ((size_t)e * 1024 + m0) * KDIM;
    const __half* Bb = B + ((size_t)e * NCOLS + n0) * KDIM;

    // ldmatrix per-thread bases (A validated R4; B 64-col validated R9/R14)
    const int xmask = (lane & 7) << 4;
    const int a_b0 = (wm * 64 + (lane & 15)) * 128 + ((lane >> 4) & 1) * 16;
    const int b_b0 = (wn * 64 + (lane & 7) + ((lane >> 4) & 1) * 8) * 128 +
                     ((lane >> 3) & 1) * 16;

    float acc[4][8][4];
#pragma unroll
    for (int i = 0; i < 4; i++)
#pragma unroll
        for (int j = 0; j < 8; j++)
#pragma unroll
            for (int q = 0; q < 4; q++) acc[i][j][q] = 0.f;

    // staging: A and B planes are 1024 16B-chunks each -> 8/thread per plane
    auto stage = [&](int kt, uint32_t base) {
        const int kofs = kt * 64;
#pragma unroll
        for (int t = 0; t < 8; t++) {
            int s = tid + (t << 7);
            int row = s >> 3, c = s & 7;
            int sw = SW128(row * 128 + c * 16);
            size_t g = (size_t)row * KDIM + kofs + c * 8;
            cp16(base + sw,         Ab + g);
            cp16(base + B_OFF + sw, Bb + g);
        }
    };

    // ---- prologue: fill stages 0,1 ----
    stage(0, smb);         CP_COMMIT();
    stage(1, smb + STAGE); CP_COMMIT();
    CP_WAIT1();            // stage 0 resident
    __syncthreads();

    for (int kt = 0; kt < NK; ++kt) {
        const uint32_t sA = smb + (kt % 3) * STAGE;

        if (kt + 2 < NK) stage(kt + 2, smb + ((kt + 2) % 3) * STAGE);
        CP_COMMIT();  // one group per iter (may be empty at tail)

#pragma unroll
        for (int k16 = 0; k16 < 4; k16++) {
            uint32_t ah[4][4], bh[4][4];
            // B frags first (gate all MMAs), then A interleaved with MMAs
#pragma unroll
            for (int nt2 = 0; nt2 < 4; nt2++) {
                int off = (b_b0 + nt2 * 2048 + k16 * 32) ^ xmask;
                ldsm4(bh[nt2], sA + B_OFF + off);
            }
            ldsm4(ah[0], sA + ((a_b0 + k16 * 32) ^ xmask));
#pragma unroll
            for (int mt = 0; mt < 4; mt++) {
                if (mt < 3) {
                    int off = (a_b0 + (mt + 1) * 2048 + k16 * 32) ^ xmask;
                    ldsm4(ah[mt + 1], sA + off);
                }
#pragma unroll
                for (int nt = 0; nt < 8; nt++) {
                    const int g = nt >> 1, s2 = (nt & 1) * 2;
                    mma_f16(acc[mt][nt], ah[mt], bh[g][s2], bh[g][s2 + 1]);
                }
            }
        }

        if (kt + 1 < NK) {
            CP_WAIT1();        // stage kt+1 resident (kt+2 in flight)
            __syncthreads();   // frees ring slot kt%3
        }
    }

    // ---- epilogue ----
    const float* bp = bias + (size_t)e * NCOLS + n0 + wn * 64;
    float2 bvv[8];
#pragma unroll
    for (int nt = 0; nt < 8; nt++)
        bvv[nt] = *(const float2*)(bp + nt * 8 + (lane & 3) * 2);

    const size_t rbase = (size_t)e * 1024 + m0 + wm * 64;
#pragma unroll
    for (int mt = 0; mt < 4; mt++) {
        int r = mt * 16 + (lane >> 2);
#pragma unroll
        for (int nt = 0; nt < 8; nt++) {
            int col = n0 + wn * 64 + nt * 8 + (lane & 3) * 2;
            float2 v0, v1;
            v0.x = acc[mt][nt][0] + bvv[nt].x;
            v0.y = acc[mt][nt][1] + bvv[nt].y;
            v1.x = acc[mt][nt][2] + bvv[nt].x;
            v1.y = acc[mt][nt][3] + bvv[nt].y;
            if (RELU) {
                v0.x = fmaxf(v0.x, 0.f); v0.y = fmaxf(v0.y, 0.f);
                v1.x = fmaxf(v1.x, 0.f); v1.y = fmaxf(v1.y, 0.f);
            }
            const size_t i0 = (rbase + r) * NCOLS + col;
            const size_t i1 = (rbase + r + 8) * NCOLS + col;
            if (HALF_OUT) {
                *(uint32_t*)(Ch + i0) = pack_h2(v0.x, v0.y);
                *(uint32_t*)(Ch + i1) = pack_h2(v1.x, v1.y);
            } else {
                *(float2*)(Cf + i0) = v0;
                *(float2*)(Cf + i1) = v1;
            }
        }
    }
}

extern "C" void kernel_launch(void* const* d_in, const int* in_sizes, int n_in,
                              void* d_out, int out_size) {
    (void)in_sizes; (void)n_in; (void)out_size;
    const float* xs = (const float*)d_in[0];
    const float* w1 = (const float*)d_in[2];
    const float* b1 = (const float*)d_in[3];
    const float* w2 = (const float*)d_in[4];
    const float* b2 = (const float*)d_in[5];
    float* out = (float*)d_out;

    void *xh, *w1h, *w2h, *hh;
    cudaGetSymbolAddress(&xh,  g_xs_h);
    cudaGetSymbolAddress(&w1h, g_w1_h);
    cudaGetSymbolAddress(&w2h, g_w2_h);
    cudaGetSymbolAddress(&hh,  g_hid_h);

    cudaFuncSetAttribute(ffn_h5<4096, 1024, true, true>,
                         cudaFuncAttributeMaxDynamicSharedMemorySize, SMEM_TOTAL);
    cudaFuncSetAttribute(ffn_h5<1024, 4096, false, false>,
                         cudaFuncAttributeMaxDynamicSharedMemorySize, SMEM_TOTAL);

    // merged prepass: xs, w1, w2 -> fp16 in one launch (bandwidth-bound)
    conv_all_k<<<147456, 256>>>((const float4*)xs, (uint2*)xh,
                                (const float4*)w1, (uint2*)w1h,
                                (const float4*)w2, (uint2*)w2h);

    // GEMM1: bias+relu, hidden written as fp16 (N=4096 -> 32 n-blocks)
    ffn_h5<4096, 1024, true, true><<<dim3(32, 8, 16), 128, SMEM_TOTAL>>>(
        (const __half*)xh, (const __half*)w1h, b1, nullptr, (__half*)hh);
    // GEMM2: bias, fp32 out (N=1024 -> 8 n-blocks)
    ffn_h5<1024, 4096, false, false><<<dim3(8, 8, 16), 128, SMEM_TOTAL>>>(
        (const __half*)hh, (const __half*)w2h, b2, out, nullptr);
}

// round 17
// speedup vs baseline: 7.7440x; 1.0725x over previous
#include <cuda_runtime.h>
#include <cuda_fp16.h>
#include <cstdint>
#include <cstddef>

// E=16, D=1024, H=4096, N=16384 (1024 tokens/expert, contiguous).
// GEMM1: per-expert [1024 x 4096 x 1024], relu(X*W1^T + b1) -> hidden (fp16)
// GEMM2: per-expert [1024 x 1024 x 4096], H*W2^T + b2       -> fp32 out
// R17 = R16 (1-pass fp16, CTA 128x128 / 4 warps / warp tile 64x64, 3x32KB
// ring, 2 CTAs/SM) + w2's fp32->fp16 conversion FUSED into GEMM1's CTAs
// (post-epilogue): GEMM1 runs at ~9% DRAM, so the 384MB of w2-convert traffic
// rides free under it; the serial prepass shrinks to xs+w1 only (~96us).

static __device__ __half g_xs_h[16777216];
static __device__ __half g_w1_h[67108864];
static __device__ __half g_w2_h[67108864];
static __device__ __half g_hid_h[67108864];

__device__ __forceinline__ uint32_t smem_u32(const void* p) {
    uint32_t a;
    asm("{ .reg .u64 t; cvta.to.shared.u64 t, %1; cvt.u32.u64 %0, t; }"
        : "=r"(a) : "l"(p));
    return a;
}
#define SW128(x) ((x) ^ (((x) >> 3) & 0x70))

// lower half = fp16(a), upper half = fp16(b)
__device__ __forceinline__ uint32_t pack_h2(float a, float b) {
    uint32_t r;
    asm("cvt.rn.f16x2.f32 %0, %1, %2;" : "=r"(r) : "f"(b), "f"(a));
    return r;
}
__device__ __forceinline__ void ldsm4(uint32_t* r, uint32_t addr) {
    asm volatile("ldmatrix.sync.aligned.m8n8.x4.shared.b16 {%0,%1,%2,%3}, [%4];"
                 : "=r"(r[0]), "=r"(r[1]), "=r"(r[2]), "=r"(r[3]) : "r"(addr));
}
__device__ __forceinline__ void mma_f16(float* c, const uint32_t* a,
                                        uint32_t b0, uint32_t b1) {
    asm volatile(
        "mma.sync.aligned.m16n8k16.row.col.f32.f16.f16.f32 "
        "{%0,%1,%2,%3}, {%4,%5,%6,%7}, {%8,%9}, {%0,%1,%2,%3};"
        : "+f"(c[0]), "+f"(c[1]), "+f"(c[2]), "+f"(c[3])
        : "r"(a[0]), "r"(a[1]), "r"(a[2]), "r"(a[3]), "r"(b0), "r"(b1));
}
__device__ __forceinline__ void cp16(uint32_t dst, const void* src) {
    asm volatile("cp.async.cg.shared.global [%0], [%1], 16;"
                 :: "r"(dst), "l"(src) : "memory");
}
#define CP_COMMIT() asm volatile("cp.async.commit_group;" ::: "memory")
#define CP_WAIT1()  asm volatile("cp.async.wait_group 1;" ::: "memory")

// -------- serial prepass: xs + w1 only (w2 fused into GEMM1) --------
// quads: xs 4194304, w1 16777216 -> total 20971520, grid 81920 x 256
__global__ __launch_bounds__(256)
void conv_xw1_k(const float4* __restrict__ xs, uint2* __restrict__ xo,
                const float4* __restrict__ w1, uint2* __restrict__ w1o) {
    int i = blockIdx.x * 256 + threadIdx.x;
    const float4* in;
    uint2* out;
    if (i < 4194304) { in = xs; out = xo; }
    else             { in = w1; out = w1o; i -= 4194304; }
    float4 f = in[i];
    out[i] = make_uint2(pack_h2(f.x, f.y), pack_h2(f.z, f.w));
}

// SMEM stage (fp16, 64-elem rows = 128B, SW128):
//   A @0 (16KB)  B @16384 (16KB)  -> 32KB/stage, 3 stages
static constexpr int B_OFF = 16384;
static constexpr int STAGE = 32768;
static constexpr int SMEM_TOTAL = 3 * STAGE;  // 96 KB -> 2 CTAs/SM

template <int NCOLS, int KDIM, bool RELU, bool HALF_OUT>
__global__ __launch_bounds__(128, 2)
void ffn_h6(const __half* __restrict__ A, const __half* __restrict__ B,
            const float* __restrict__ bias,
            float* __restrict__ Cf, __half* __restrict__ Ch,
            const float4* __restrict__ w2f, uint2* __restrict__ w2h)
{
    constexpr int NK = KDIM / 64;
    extern __shared__ char smem[];
    const uint32_t smb = smem_u32(smem);

    const int tid  = threadIdx.x;
    const int lane = tid & 31, warp = tid >> 5;   // 4 warps
    const int wm = warp >> 1, wn = warp & 1;      // 2x2, warp tile 64(M) x 64(N)
    const int e  = blockIdx.z;
    const int m0 = blockIdx.y * 128, n0 = blockIdx.x * 128;

    const __half* Ab = A + ((size_t)e * 1024 + m0) * KDIM;
    const __half* Bb = B + ((size_t)e * NCOLS + n0) * KDIM;

    // ldmatrix per-thread bases (A validated R4; B 64-col validated R9/R14)
    const int xmask = (lane & 7) << 4;
    const int a_b0 = (wm * 64 + (lane & 15)) * 128 + ((lane >> 4) & 1) * 16;
    const int b_b0 = (wn * 64 + (lane & 7) + ((lane >> 4) & 1) * 8) * 128 +
                     ((lane >> 3) & 1) * 16;

    float acc[4][8][4];
#pragma unroll
    for (int i = 0; i < 4; i++)
#pragma unroll
        for (int j = 0; j < 8; j++)
#pragma unroll
            for (int q = 0; q < 4; q++) acc[i][j][q] = 0.f;

    // staging: A and B planes are 1024 16B-chunks each -> 8/thread per plane
    auto stage = [&](int kt, uint32_t base) {
        const int kofs = kt * 64;
#pragma unroll
        for (int t = 0; t < 8; t++) {
            int s = tid + (t << 7);
            int row = s >> 3, c = s & 7;
            int sw = SW128(row * 128 + c * 16);
            size_t g = (size_t)row * KDIM + kofs + c * 8;
            cp16(base + sw,         Ab + g);
            cp16(base + B_OFF + sw, Bb + g);
        }
    };

    // ---- prologue: fill stages 0,1 ----
    stage(0, smb);         CP_COMMIT();
    stage(1, smb + STAGE); CP_COMMIT();
    CP_WAIT1();            // stage 0 resident
    __syncthreads();

    for (int kt = 0; kt < NK; ++kt) {
        const uint32_t sA = smb + (kt % 3) * STAGE;

        if (kt + 2 < NK) stage(kt + 2, smb + ((kt + 2) % 3) * STAGE);
        CP_COMMIT();  // one group per iter (may be empty at tail)

#pragma unroll
        for (int k16 = 0; k16 < 4; k16++) {
            uint32_t ah[4][4], bh[4][4];
            // B frags first (gate all MMAs), then A interleaved with MMAs
#pragma unroll
            for (int nt2 = 0; nt2 < 4; nt2++) {
                int off = (b_b0 + nt2 * 2048 + k16 * 32) ^ xmask;
                ldsm4(bh[nt2], sA + B_OFF + off);
            }
            ldsm4(ah[0], sA + ((a_b0 + k16 * 32) ^ xmask));
#pragma unroll
            for (int mt = 0; mt < 4; mt++) {
                if (mt < 3) {
                    int off = (a_b0 + (mt + 1) * 2048 + k16 * 32) ^ xmask;
                    ldsm4(ah[mt + 1], sA + off);
                }
#pragma unroll
                for (int nt = 0; nt < 8; nt++) {
                    const int g = nt >> 1, s2 = (nt & 1) * 2;
                    mma_f16(acc[mt][nt], ah[mt], bh[g][s2], bh[g][s2 + 1]);
                }
            }
        }

        if (kt + 1 < NK) {
            CP_WAIT1();        // stage kt+1 resident (kt+2 in flight)
            __syncthreads();   // frees ring slot kt%3
        }
    }

    // ---- epilogue ----
    const float* bp = bias + (size_t)e * NCOLS + n0 + wn * 64;
    float2 bvv[8];
#pragma unroll
    for (int nt = 0; nt < 8; nt++)
        bvv[nt] = *(const float2*)(bp + nt * 8 + (lane & 3) * 2);

    const size_t rbase = (size_t)e * 1024 + m0 + wm * 64;
#pragma unroll
    for (int mt = 0; mt < 4; mt++) {
        int r = mt * 16 + (lane >> 2);
#pragma unroll
        for (int nt = 0; nt < 8; nt++) {
            int col = n0 + wn * 64 + nt * 8 + (lane & 3) * 2;
            float2 v0, v1;
            v0.x = acc[mt][nt][0] + bvv[nt].x;
            v0.y = acc[mt][nt][1] + bvv[nt].y;
            v1.x = acc[mt][nt][2] + bvv[nt].x;
            v1.y = acc[mt][nt][3] + bvv[nt].y;
            if (RELU) {
                v0.x = fmaxf(v0.x, 0.f); v0.y = fmaxf(v0.y, 0.f);
                v1.x = fmaxf(v1.x, 0.f); v1.y = fmaxf(v1.y, 0.f);
            }
            const size_t i0 = (rbase + r) * NCOLS + col;
            const size_t i1 = (rbase + r + 8) * NCOLS + col;
            if (HALF_OUT) {
                *(uint32_t*)(Ch + i0) = pack_h2(v0.x, v0.y);
                *(uint32_t*)(Ch + i1) = pack_h2(v1.x, v1.y);
            } else {
                *(float2*)(Cf + i0) = v0;
                *(float2*)(Cf + i1) = v1;
            }
        }
    }

    // ---- fused w2 convert (GEMM1 only): 16777216 quads over 4096 CTAs ----
    // Rides GEMM1's idle DRAM bandwidth (~9% busy); must finish before GEMM2
    // launches, which the kernel boundary guarantees.
    if (HALF_OUT) {
        const int bid = blockIdx.x + gridDim.x * (blockIdx.y + 8 * blockIdx.z);
        const size_t qbase = (size_t)bid * 4096 + tid;
#pragma unroll
        for (int t = 0; t < 32; t++) {
            const size_t q = qbase + (size_t)t * 128;
            float4 f = w2f[q];
            w2h[q] = make_uint2(pack_h2(f.x, f.y), pack_h2(f.z, f.w));
        }
    }
}

extern "C" void kernel_launch(void* const* d_in, const int* in_sizes, int n_in,
                              void* d_out, int out_size) {
    (void)in_sizes; (void)n_in; (void)out_size;
    const float* xs = (const float*)d_in[0];
    const float* w1 = (const float*)d_in[2];
    const float* b1 = (const float*)d_in[3];
    const float* w2 = (const float*)d_in[4];
    const float* b2 = (const float*)d_in[5];
    float* out = (float*)d_out;

    void *xh, *w1h, *w2h, *hh;
    cudaGetSymbolAddress(&xh,  g_xs_h);
    cudaGetSymbolAddress(&w1h, g_w1_h);
    cudaGetSymbolAddress(&w2h, g_w2_h);
    cudaGetSymbolAddress(&hh,  g_hid_h);

    cudaFuncSetAttribute(ffn_h6<4096, 1024, true, true>,
                         cudaFuncAttributeMaxDynamicSharedMemorySize, SMEM_TOTAL);
    cudaFuncSetAttribute(ffn_h6<1024, 4096, false, false>,
                         cudaFuncAttributeMaxDynamicSharedMemorySize, SMEM_TOTAL);

    // serial prepass: xs + w1 only
    conv_xw1_k<<<81920, 256>>>((const float4*)xs, (uint2*)xh,
                               (const float4*)w1, (uint2*)w1h);

    // GEMM1: bias+relu -> fp16 hidden; ALSO converts w2 fp32->fp16 (fused)
    ffn_h6<4096, 1024, true, true><<<dim3(32, 8, 16), 128, SMEM_TOTAL>>>(
        (const __half*)xh, (const __half*)w1h, b1, nullptr, (__half*)hh,
        (const float4*)w2, (uint2*)w2h);
    // GEMM2: bias -> fp32 out
    ffn_h6<1024, 4096, false, false><<<dim3(8, 8, 16), 128, SMEM_TOTAL>>>(
        (const __half*)hh, (const __half*)w2h, b2, out, nullptr,
        nullptr, nullptr);
}